// round 2
// baseline (speedup 1.0000x reference)
#include <cuda_runtime.h>
#include <math.h>

// ---------------------------------------------------------------------------
// CATB axial attention block, fp32 + packed f32x2 (FFMA2) version.
// ---------------------------------------------------------------------------

#define BATCH 2
#define HH 112
#define WW 112
#define CC 192
#define LL (HH * WW)          // 12544
#define MROWS (BATCH * LL)    // 25088
#define CB 96
#define HD_ 24
#define NHB 4
#define NTOK 784              // 112*7
#define NPOS 2899             // (2*112-1)*(2*7-1)
#define HIDDEN 768

// -------------------------- scratch (device globals) -----------------------
__device__ float g_img[MROWS * CC];
__device__ float g_qkv[MROWS * 3 * CC];
__device__ float g_att[MROWS * CC];
__device__ float g_xo [MROWS * CC];
__device__ float g_y  [MROWS * CC];
__device__ float g_h  [MROWS * HIDDEN];
__device__ float g_pos[2 * NPOS * NHB];

// -------------------------- f32x2 helpers ----------------------------------
__device__ __forceinline__ void ffma2(unsigned long long& c,
                                      unsigned long long a,
                                      unsigned long long b)
{
    asm("fma.rn.f32x2 %0, %1, %2, %0;" : "+l"(c) : "l"(a), "l"(b));
}
__device__ __forceinline__ unsigned long long pack2(float lo, float hi)
{
    unsigned long long r;
    asm("mov.b64 %0, {%1, %2};" : "=l"(r) : "f"(lo), "f"(hi));
    return r;
}
__device__ __forceinline__ float lo2(unsigned long long v)
{ return __uint_as_float((unsigned)v); }
__device__ __forceinline__ float hi2(unsigned long long v)
{ return __uint_as_float((unsigned)(v >> 32)); }

// -------------------------- LayerNorm over C=192 ---------------------------
__global__ __launch_bounds__(256) void ln_kernel(
    const float* __restrict__ in, const float* __restrict__ w,
    const float* __restrict__ b, float* __restrict__ out)
{
    int row = blockIdx.x * 8 + (threadIdx.x >> 5);
    if (row >= MROWS) return;
    int lane = threadIdx.x & 31;
    const float* p = in + (long)row * CC;
    float v[6];
    float s = 0.f, s2 = 0.f;
#pragma unroll
    for (int u = 0; u < 6; u++) {
        v[u] = p[lane + u * 32];
        s += v[u];
        s2 += v[u] * v[u];
    }
#pragma unroll
    for (int off = 16; off > 0; off >>= 1) {
        s  += __shfl_xor_sync(0xffffffffu, s,  off);
        s2 += __shfl_xor_sync(0xffffffffu, s2, off);
    }
    float mu  = s * (1.f / CC);
    float var = s2 * (1.f / CC) - mu * mu;
    float inv = rsqrtf(var + 1e-5f);
    float* q = out + (long)row * CC;
#pragma unroll
    for (int u = 0; u < 6; u++) {
        int c = lane + u * 32;
        q[c] = (v[u] - mu) * inv * w[c] + b[c];
    }
}

// -------------------------- rel-pos-bias MLP -------------------------------
__device__ __forceinline__ void ln6_relu(float* v, const float* w, const float* b)
{
    float mu = 0.f;
#pragma unroll
    for (int i = 0; i < 6; i++) mu += v[i];
    mu *= (1.f / 6.f);
    float var = 0.f;
#pragma unroll
    for (int i = 0; i < 6; i++) { float d = v[i] - mu; var += d * d; }
    var *= (1.f / 6.f);
    float inv = rsqrtf(var + 1e-5f);
#pragma unroll
    for (int i = 0; i < 6; i++)
        v[i] = fmaxf((v[i] - mu) * inv * w[i] + b[i], 0.f);
}

__global__ void pos_mlp_kernel(
    const float* __restrict__ proj_w, const float* __restrict__ proj_b,
    const float* __restrict__ ln1_w,  const float* __restrict__ ln1_b,
    const float* __restrict__ fc1_w,  const float* __restrict__ fc1_b,
    const float* __restrict__ ln2_w,  const float* __restrict__ ln2_b,
    const float* __restrict__ fc2_w,  const float* __restrict__ fc2_b,
    const float* __restrict__ ln3_w,  const float* __restrict__ ln3_b,
    const float* __restrict__ fc3_w,  const float* __restrict__ fc3_b,
    float* __restrict__ out)
{
    int idx = blockIdx.x * blockDim.x + threadIdx.x;
    if (idx >= 2 * NPOS) return;
    int br = idx / NPOS, r = idx - br * NPOS;
    int Hsp = br ? 7 : 112;
    int Wsp = br ? 112 : 7;
    int W2 = 2 * Wsp - 1;
    int a = r / W2, bcol = r - a * W2;
    float ph = (float)(a - (Hsp - 1));
    float pw = (float)(bcol - (Wsp - 1));

    float t[6], u[6];
#pragma unroll
    for (int o = 0; o < 6; o++)
        t[o] = proj_w[(br * 6 + o) * 2 + 0] * ph +
               proj_w[(br * 6 + o) * 2 + 1] * pw + proj_b[br * 6 + o];
    ln6_relu(t, ln1_w + br * 6, ln1_b + br * 6);
#pragma unroll
    for (int o = 0; o < 6; o++) {
        float s = fc1_b[br * 6 + o];
#pragma unroll
        for (int i = 0; i < 6; i++) s += fc1_w[br * 36 + o * 6 + i] * t[i];
        u[o] = s;
    }
    ln6_relu(u, ln2_w + br * 6, ln2_b + br * 6);
#pragma unroll
    for (int o = 0; o < 6; o++) {
        float s = fc2_b[br * 6 + o];
#pragma unroll
        for (int i = 0; i < 6; i++) s += fc2_w[br * 36 + o * 6 + i] * u[i];
        t[o] = s;
    }
    ln6_relu(t, ln3_w + br * 6, ln3_b + br * 6);
#pragma unroll
    for (int h = 0; h < 4; h++) {
        float s = fc3_b[br * 4 + h];
#pragma unroll
        for (int i = 0; i < 6; i++) s += fc3_w[br * 24 + h * 6 + i] * t[i];
        out[(br * NPOS + r) * 4 + h] = s;
    }
}

// -------------------------- attention --------------------------------------
// 512 blocks: bx = ((br*128 + win*4 + head) << 1) | queryhalf.
// SMEM: K[784*24], V[784*24], pos column[2899].  Scores live in registers.
#define ATTN_SMEM ((2 * NTOK * HD_ + NPOS) * 4)
#define NT 25   // score slots per lane (784 = 24*32 + 16)

__global__ __launch_bounds__(256) void attn_kernel(
    const float* __restrict__ qkv, const float* __restrict__ pos,
    float* __restrict__ att_out)
{
    extern __shared__ float sm[];
    float* Ks = sm;                          // 784*24
    float* Vs = Ks + NTOK * HD_;             // 784*24
    float* Ps = Vs + NTOK * HD_;             // 2899

    int bx    = blockIdx.x;
    int half  = bx & 1;
    int r     = bx >> 1;
    int br    = r >> 7;
    int rem   = r & 127;
    int win   = rem >> 2;
    int head  = rem & 3;
    int b     = win >> 4, w16 = win & 15;
    int tid   = threadIdx.x, lane = tid & 31, warp = tid >> 5;
    int cbase = br * CB + head * HD_;

    // load K, V for this (window, head) into smem
    for (int idx = tid; idx < NTOK * HD_; idx += 256) {
        int j = idx / HD_, d = idx - j * HD_;
        int h, w;
        if (br == 0) { int hj = j / 7;   h = hj;           w = w16 * 7 + (j - hj * 7); }
        else         { int hj = j / 112; h = w16 * 7 + hj; w = j - hj * 112; }
        long base = ((long)(b * LL + h * WW + w)) * 576 + cbase + d;
        Ks[j * HD_ + d] = qkv[base + 192];
        Vs[j * HD_ + d] = qkv[base + 384];
    }
    for (int rr = tid; rr < NPOS; rr += 256)
        Ps[rr] = pos[(br * NPOS + rr) * 4 + head];
    __syncthreads();

    const float scale = 0.20412414523193154f; // 24^-0.5
    const int Hsp = br ? 7 : 112;
    const int Wsp = br ? 112 : 7;
    const int W2  = 2 * Wsp - 1;
    const int qbase = half * (NTOK / 2);

    for (int i0 = qbase + warp * 2; i0 < qbase + NTOK / 2; i0 += 16) {
        int i1 = i0 + 1;
        int hi0, wi0, l0, hi1, wi1, l1;
        if (br == 0) {
            hi0 = i0 / 7; wi0 = i0 - hi0 * 7; l0 = hi0 * WW + w16 * 7 + wi0;
            hi1 = i1 / 7; wi1 = i1 - hi1 * 7; l1 = hi1 * WW + w16 * 7 + wi1;
        } else {
            hi0 = i0 / 112; wi0 = i0 - hi0 * 112; l0 = (w16 * 7 + hi0) * WW + wi0;
            hi1 = i1 / 112; wi1 = i1 - hi1 * 112; l1 = (w16 * 7 + hi1) * WW + wi1;
        }
        // q pairs over d (12 packed f32x2 per row), pre-scaled
        unsigned long long q0p[12], q1p[12];
        {
            const float* qp0 = qkv + ((long)(b * LL + l0)) * 576 + cbase;
            const float* qp1 = qkv + ((long)(b * LL + l1)) * 576 + cbase;
#pragma unroll
            for (int dp = 0; dp < 12; dp++) {
                q0p[dp] = pack2(qp0[2 * dp] * scale, qp0[2 * dp + 1] * scale);
                q1p[dp] = pack2(qp1[2 * dp] * scale, qp1[2 * dp + 1] * scale);
            }
        }
        int rb0 = (hi0 + Hsp - 1) * W2 + wi0 + Wsp - 1;
        int rb1 = (hi1 + Hsp - 1) * W2 + wi1 + Wsp - 1;

        float s0[NT], s1[NT];
        float m0 = -1e30f, m1 = -1e30f;
#pragma unroll
        for (int t = 0; t < NT; t++) {
            int j = lane + t * 32;
            if (t == NT - 1 && lane >= 16) { s0[t] = -1e30f; s1[t] = -1e30f; continue; }
            const ulonglong2* kp = (const ulonglong2*)(Ks + j * HD_);
            unsigned long long ps0 = 0ull, ps1 = 0ull;
#pragma unroll
            for (int q4 = 0; q4 < 6; q4++) {
                ulonglong2 kk = kp[q4];
                ffma2(ps0, kk.x, q0p[q4 * 2]);     ffma2(ps1, kk.x, q1p[q4 * 2]);
                ffma2(ps0, kk.y, q0p[q4 * 2 + 1]); ffma2(ps1, kk.y, q1p[q4 * 2 + 1]);
            }
            int hj, wj;
            if (br == 0) { hj = j / 7;   wj = j - hj * 7;   }
            else         { hj = j / 112; wj = j - hj * 112; }
            int roff = hj * W2 + wj;
            float a0 = lo2(ps0) + hi2(ps0) + Ps[rb0 - roff];
            float a1 = lo2(ps1) + hi2(ps1) + Ps[rb1 - roff];
            s0[t] = a0; s1[t] = a1;
            m0 = fmaxf(m0, a0); m1 = fmaxf(m1, a1);
        }
#pragma unroll
        for (int off = 16; off > 0; off >>= 1) {
            m0 = fmaxf(m0, __shfl_xor_sync(0xffffffffu, m0, off));
            m1 = fmaxf(m1, __shfl_xor_sync(0xffffffffu, m1, off));
        }
        float e0 = 0.f, e1 = 0.f;
#pragma unroll
        for (int t = 0; t < NT; t++) {
            if (t == NT - 1 && lane >= 16) { s0[t] = 0.f; s1[t] = 0.f; continue; }
            float p = __expf(s0[t] - m0); s0[t] = p; e0 += p;
            p = __expf(s1[t] - m1);       s1[t] = p; e1 += p;
        }
#pragma unroll
        for (int off = 16; off > 0; off >>= 1) {
            e0 += __shfl_xor_sync(0xffffffffu, e0, off);
            e1 += __shfl_xor_sync(0xffffffffu, e1, off);
        }
        float inv0 = 1.f / e0, inv1 = 1.f / e1;

        unsigned long long acc0[12], acc1[12];
#pragma unroll
        for (int dp = 0; dp < 12; dp++) { acc0[dp] = 0ull; acc1[dp] = 0ull; }
#pragma unroll
        for (int t = 0; t < NT; t++) {
            int j = lane + t * 32;
            if (t == NT - 1 && lane >= 16) continue;
            unsigned long long p0 = pack2(s0[t], s0[t]);
            unsigned long long p1 = pack2(s1[t], s1[t]);
            const ulonglong2* vp = (const ulonglong2*)(Vs + j * HD_);
#pragma unroll
            for (int q4 = 0; q4 < 6; q4++) {
                ulonglong2 vv = vp[q4];
                ffma2(acc0[q4 * 2],     vv.x, p0); ffma2(acc1[q4 * 2],     vv.x, p1);
                ffma2(acc0[q4 * 2 + 1], vv.y, p0); ffma2(acc1[q4 * 2 + 1], vv.y, p1);
            }
        }
        // unpack, butterfly-reduce across lanes
        float a0f[24], a1f[24];
#pragma unroll
        for (int dp = 0; dp < 12; dp++) {
            a0f[2 * dp] = lo2(acc0[dp]); a0f[2 * dp + 1] = hi2(acc0[dp]);
            a1f[2 * dp] = lo2(acc1[dp]); a1f[2 * dp + 1] = hi2(acc1[dp]);
        }
#pragma unroll
        for (int d = 0; d < 24; d++) {
#pragma unroll
            for (int off = 16; off > 0; off >>= 1) {
                a0f[d] += __shfl_xor_sync(0xffffffffu, a0f[d], off);
                a1f[d] += __shfl_xor_sync(0xffffffffu, a1f[d], off);
            }
        }
        if (lane < 12) {
            int rsel = lane >= 6;
            int d4 = rsel ? lane - 6 : lane;
            const float* af = rsel ? a1f : a0f;
            float invv = rsel ? inv1 : inv0;
            long ll = rsel ? l1 : l0;
            float* o = att_out + ((long)(b * LL) + ll) * CC + cbase + d4 * 4;
            *(float4*)o = make_float4(af[d4*4+0]*invv, af[d4*4+1]*invv,
                                      af[d4*4+2]*invv, af[d4*4+3]*invv);
        }
    }
}

// -------------------------- SGEMM (NT) with FFMA2 --------------------------
// out[M,N] = A[M,K] @ W[N,K]^T.  BM=128, BN=64, BK=16, 256 thr, 8x4 microtile
// computed as 4 row-pairs x 4 cols in packed f32x2.
// MODE 0: plain. 1: +bias +res. 2: +bias, gelu. 3: +bias +res.
__device__ __forceinline__ float gelu_f(float x)
{
    return 0.5f * x * (1.f + erff(x * 0.7071067811865476f));
}

template <int MODE>
__global__ __launch_bounds__(256) void gemm_kernel(
    const float* __restrict__ A, const float* __restrict__ Wt,
    const float* __restrict__ bias, const float* __restrict__ res,
    float* __restrict__ out, int N, int K)
{
    __shared__ __align__(16) float As[16][128];
    __shared__ __align__(16) float Bs[16][128];   // duplicated pairs {b,b}
    const int m0 = blockIdx.x * 128;
    const int n0 = blockIdx.y * 64;
    const int tid = threadIdx.x;
    const int tx = tid & 15, ty = tid >> 4;

    unsigned long long c2[4][4];
#pragma unroll
    for (int u = 0; u < 4; u++)
#pragma unroll
        for (int v = 0; v < 4; v++) c2[u][v] = 0ull;

    for (int kt = 0; kt < K; kt += 16) {
#pragma unroll
        for (int i = 0; i < 2; i++) {
            int f = tid + i * 256;
            int m = f >> 2, k4 = (f & 3) * 4;
            float4 a = *(const float4*)&A[(long)(m0 + m) * K + kt + k4];
            As[k4 + 0][m] = a.x; As[k4 + 1][m] = a.y;
            As[k4 + 2][m] = a.z; As[k4 + 3][m] = a.w;
        }
        {
            int n = tid >> 2, k4 = (tid & 3) * 4;
            float4 bv = *(const float4*)&Wt[(long)(n0 + n) * K + kt + k4];
            *(float2*)&Bs[k4 + 0][2 * n] = make_float2(bv.x, bv.x);
            *(float2*)&Bs[k4 + 1][2 * n] = make_float2(bv.y, bv.y);
            *(float2*)&Bs[k4 + 2][2 * n] = make_float2(bv.z, bv.z);
            *(float2*)&Bs[k4 + 3][2 * n] = make_float2(bv.w, bv.w);
        }
        __syncthreads();
#pragma unroll
        for (int kk = 0; kk < 16; kk++) {
            ulonglong2 aA = *(const ulonglong2*)&As[kk][ty * 8];
            ulonglong2 aB = *(const ulonglong2*)&As[kk][ty * 8 + 4];
            ulonglong2 bA = *(const ulonglong2*)&Bs[kk][tx * 8];
            ulonglong2 bB = *(const ulonglong2*)&Bs[kk][tx * 8 + 4];
            unsigned long long ar[4] = {aA.x, aA.y, aB.x, aB.y};
            unsigned long long br[4] = {bA.x, bA.y, bB.x, bB.y};
#pragma unroll
            for (int u = 0; u < 4; u++)
#pragma unroll
                for (int v = 0; v < 4; v++) ffma2(c2[u][v], ar[u], br[v]);
        }
        __syncthreads();
    }

    float4 bb = make_float4(0.f, 0.f, 0.f, 0.f);
    if (MODE >= 1) bb = *(const float4*)&bias[n0 + tx * 4];
#pragma unroll
    for (int u = 0; u < 4; u++) {
#pragma unroll
        for (int rsel = 0; rsel < 2; rsel++) {
            int row = m0 + ty * 8 + 2 * u + rsel;
            long rowoff = (long)row * N + n0 + tx * 4;
            float4 o;
            o.x = rsel ? hi2(c2[u][0]) : lo2(c2[u][0]);
            o.y = rsel ? hi2(c2[u][1]) : lo2(c2[u][1]);
            o.z = rsel ? hi2(c2[u][2]) : lo2(c2[u][2]);
            o.w = rsel ? hi2(c2[u][3]) : lo2(c2[u][3]);
            if (MODE >= 1) { o.x += bb.x; o.y += bb.y; o.z += bb.z; o.w += bb.w; }
            if (MODE == 1 || MODE == 3) {
                float4 rr = *(const float4*)&res[rowoff];
                o.x += rr.x; o.y += rr.y; o.z += rr.z; o.w += rr.w;
            }
            if (MODE == 2) {
                o.x = gelu_f(o.x); o.y = gelu_f(o.y);
                o.z = gelu_f(o.z); o.w = gelu_f(o.w);
            }
            *(float4*)&out[rowoff] = o;
        }
    }
}

// -------------------------- launch -----------------------------------------
extern "C" void kernel_launch(void* const* d_in, const int* in_sizes, int n_in,
                              void* d_out, int out_size)
{
    const float* x      = (const float*)d_in[0];
    const float* n1w    = (const float*)d_in[1];
    const float* n1b    = (const float*)d_in[2];
    const float* qkv_w  = (const float*)d_in[3];
    const float* proj_w = (const float*)d_in[4];
    const float* proj_b = (const float*)d_in[5];
    const float* n2w    = (const float*)d_in[6];
    const float* n2b    = (const float*)d_in[7];
    const float* fc1_w  = (const float*)d_in[8];
    const float* fc1_b  = (const float*)d_in[9];
    const float* fc2_w  = (const float*)d_in[10];
    const float* fc2_b  = (const float*)d_in[11];
    const float* pproj_w = (const float*)d_in[12];
    const float* pproj_b = (const float*)d_in[13];
    const float* pln1_w = (const float*)d_in[14];
    const float* pln1_b = (const float*)d_in[15];
    const float* pfc1_w = (const float*)d_in[16];
    const float* pfc1_b = (const float*)d_in[17];
    const float* pln2_w = (const float*)d_in[18];
    const float* pln2_b = (const float*)d_in[19];
    const float* pfc2_w = (const float*)d_in[20];
    const float* pfc2_b = (const float*)d_in[21];
    const float* pln3_w = (const float*)d_in[22];
    const float* pln3_b = (const float*)d_in[23];
    const float* pfc3_w = (const float*)d_in[24];
    const float* pfc3_b = (const float*)d_in[25];
    float* out = (float*)d_out;

    float *img, *qkvb, *att, *xo, *y, *hbuf, *pos;
    cudaGetSymbolAddress((void**)&img,  g_img);
    cudaGetSymbolAddress((void**)&qkvb, g_qkv);
    cudaGetSymbolAddress((void**)&att,  g_att);
    cudaGetSymbolAddress((void**)&xo,   g_xo);
    cudaGetSymbolAddress((void**)&y,    g_y);
    cudaGetSymbolAddress((void**)&hbuf, g_h);
    cudaGetSymbolAddress((void**)&pos,  g_pos);

    cudaFuncSetAttribute(attn_kernel,
                         cudaFuncAttributeMaxDynamicSharedMemorySize, ATTN_SMEM);

    // 1. relative-position-bias tables (2 x 2899 x 4)
    pos_mlp_kernel<<<(2 * NPOS + 127) / 128, 128>>>(
        pproj_w, pproj_b, pln1_w, pln1_b, pfc1_w, pfc1_b,
        pln2_w, pln2_b, pfc2_w, pfc2_b, pln3_w, pln3_b, pfc3_w, pfc3_b, pos);
    // 2. LN1
    ln_kernel<<<MROWS / 8, 256>>>(x, n1w, n1b, img);
    // 3. qkv projection: (25088,192) @ (576,192)^T
    gemm_kernel<0><<<dim3(MROWS / 128, 576 / 64), 256>>>(
        img, qkv_w, nullptr, nullptr, qkvb, 576, 192);
    // 4. axial window attention, both branches, query-split x2
    attn_kernel<<<512, 256, ATTN_SMEM>>>(qkvb, pos, att);
    // 5. proj + residual -> xo
    gemm_kernel<1><<<dim3(MROWS / 128, 192 / 64), 256>>>(
        att, proj_w, proj_b, x, xo, 192, 192);
    // 6. LN2
    ln_kernel<<<MROWS / 8, 256>>>(xo, n2w, n2b, y);
    // 7. fc1 + gelu
    gemm_kernel<2><<<dim3(MROWS / 128, HIDDEN / 64), 256>>>(
        y, fc1_w, fc1_b, nullptr, hbuf, HIDDEN, 192);
    // 8. fc2 + bias + residual -> out
    gemm_kernel<3><<<dim3(MROWS / 128, 192 / 64), 256>>>(
        hbuf, fc2_w, fc2_b, xo, out, 192, HIDDEN);
}

// round 4
// speedup vs baseline: 2.0559x; 2.0559x over previous
#include <cuda_runtime.h>
#include <math.h>

// ---------------------------------------------------------------------------
// CATB axial attention block. fp32, FFMA2 (f32x2) everywhere hot.
// ---------------------------------------------------------------------------

#define BATCH 2
#define HH 112
#define WW 112
#define CC 192
#define LL (HH * WW)          // 12544
#define MROWS (BATCH * LL)    // 25088
#define CB 96
#define HD_ 24
#define NTOK 784              // 112*7
#define NPOS 2899             // (2*112-1)*(2*7-1)
#define HIDDEN 768

typedef unsigned long long u64;

// -------------------------- scratch (device globals) -----------------------
__device__ float g_img[MROWS * CC];
__device__ float g_qkv[MROWS * 3 * CC];
__device__ float g_att[MROWS * CC];
__device__ float g_xo [MROWS * CC];
__device__ float g_y  [MROWS * CC];
__device__ float g_h  [MROWS * HIDDEN];
__device__ float g_pos[2 * NPOS * 4];

// -------------------------- f32x2 helpers ----------------------------------
__device__ __forceinline__ void ffma2(u64& c, u64 a, u64 b)
{
    asm("fma.rn.f32x2 %0, %1, %2, %0;" : "+l"(c) : "l"(a), "l"(b));
}
__device__ __forceinline__ void mul2(u64& c, u64 a)
{
    asm("mul.rn.f32x2 %0, %0, %1;" : "+l"(c) : "l"(a));
}
__device__ __forceinline__ u64 pack2(float lo, float hi)
{
    u64 r;
    asm("mov.b64 %0, {%1, %2};" : "=l"(r) : "f"(lo), "f"(hi));
    return r;
}
__device__ __forceinline__ float lo2(u64 v) { return __uint_as_float((unsigned)v); }
__device__ __forceinline__ float hi2(u64 v) { return __uint_as_float((unsigned)(v >> 32)); }

// -------------------------- LayerNorm over C=192 ---------------------------
__global__ __launch_bounds__(256) void ln_kernel(
    const float* __restrict__ in, const float* __restrict__ w,
    const float* __restrict__ b, float* __restrict__ out)
{
    int row = blockIdx.x * 8 + (threadIdx.x >> 5);
    if (row >= MROWS) return;
    int lane = threadIdx.x & 31;
    const float* p = in + (long)row * CC;
    float v[6];
    float s = 0.f, s2 = 0.f;
#pragma unroll
    for (int u = 0; u < 6; u++) {
        v[u] = p[lane + u * 32];
        s += v[u];
        s2 += v[u] * v[u];
    }
#pragma unroll
    for (int off = 16; off > 0; off >>= 1) {
        s  += __shfl_xor_sync(0xffffffffu, s,  off);
        s2 += __shfl_xor_sync(0xffffffffu, s2, off);
    }
    float mu  = s * (1.f / CC);
    float var = s2 * (1.f / CC) - mu * mu;
    float inv = rsqrtf(var + 1e-5f);
    float* q = out + (long)row * CC;
#pragma unroll
    for (int u = 0; u < 6; u++) {
        int c = lane + u * 32;
        q[c] = (v[u] - mu) * inv * w[c] + b[c];
    }
}

// -------------------------- rel-pos-bias MLP -------------------------------
__device__ __forceinline__ void ln6_relu(float* v, const float* w, const float* b)
{
    float mu = 0.f;
#pragma unroll
    for (int i = 0; i < 6; i++) mu += v[i];
    mu *= (1.f / 6.f);
    float var = 0.f;
#pragma unroll
    for (int i = 0; i < 6; i++) { float d = v[i] - mu; var += d * d; }
    var *= (1.f / 6.f);
    float inv = rsqrtf(var + 1e-5f);
#pragma unroll
    for (int i = 0; i < 6; i++)
        v[i] = fmaxf((v[i] - mu) * inv * w[i] + b[i], 0.f);
}

__global__ void pos_mlp_kernel(
    const float* __restrict__ proj_w, const float* __restrict__ proj_b,
    const float* __restrict__ ln1_w,  const float* __restrict__ ln1_b,
    const float* __restrict__ fc1_w,  const float* __restrict__ fc1_b,
    const float* __restrict__ ln2_w,  const float* __restrict__ ln2_b,
    const float* __restrict__ fc2_w,  const float* __restrict__ fc2_b,
    const float* __restrict__ ln3_w,  const float* __restrict__ ln3_b,
    const float* __restrict__ fc3_w,  const float* __restrict__ fc3_b,
    float* __restrict__ out)
{
    int idx = blockIdx.x * blockDim.x + threadIdx.x;
    if (idx >= 2 * NPOS) return;
    int br = idx / NPOS, r = idx - br * NPOS;
    int Hsp = br ? 7 : 112;
    int Wsp = br ? 112 : 7;
    int W2 = 2 * Wsp - 1;
    int a = r / W2, bcol = r - a * W2;
    float ph = (float)(a - (Hsp - 1));
    float pw = (float)(bcol - (Wsp - 1));

    float t[6], u[6];
#pragma unroll
    for (int o = 0; o < 6; o++)
        t[o] = proj_w[(br * 6 + o) * 2 + 0] * ph +
               proj_w[(br * 6 + o) * 2 + 1] * pw + proj_b[br * 6 + o];
    ln6_relu(t, ln1_w + br * 6, ln1_b + br * 6);
#pragma unroll
    for (int o = 0; o < 6; o++) {
        float s = fc1_b[br * 6 + o];
#pragma unroll
        for (int i = 0; i < 6; i++) s += fc1_w[br * 36 + o * 6 + i] * t[i];
        u[o] = s;
    }
    ln6_relu(u, ln2_w + br * 6, ln2_b + br * 6);
#pragma unroll
    for (int o = 0; o < 6; o++) {
        float s = fc2_b[br * 6 + o];
#pragma unroll
        for (int i = 0; i < 6; i++) s += fc2_w[br * 36 + o * 6 + i] * u[i];
        t[o] = s;
    }
    ln6_relu(t, ln3_w + br * 6, ln3_b + br * 6);
#pragma unroll
    for (int h = 0; h < 4; h++) {
        float s = fc3_b[br * 4 + h];
#pragma unroll
        for (int i = 0; i < 6; i++) s += fc3_w[br * 24 + h * 6 + i] * t[i];
        out[(br * NPOS + r) * 4 + h] = s;
    }
}

// -------------------------- attention --------------------------------------
// 256 blocks = (branch, window, head). Lanes own query rows; K/V rows are
// broadcast-read from SMEM (conflict-free). Online softmax, chunked by 8 keys.
#define ATTN_SMEM ((2 * NTOK * HD_ + NPOS + NTOK) * 4)

template <int ROWS>
__device__ __forceinline__ void attn_pass(
    int start, int lane, int br, int b, int w16, int cbase,
    const float* __restrict__ qkv, const float* Ks, const float* Vs,
    const float* Ps, const int* Rj, float* __restrict__ att_out,
    int Hsp, int Wsp, int W2)
{
    const float scale = 0.20412414523193154f; // 24^-0.5

    int rA = start + lane;
    bool actA = rA < NTOK;
    int rAc = actA ? rA : NTOK - 1;
    int rB = rA + 32;
    bool actB = (ROWS == 2) && (rB < NTOK);
    int rBc = actB ? rB : NTOK - 1;

    int hiA, wiA, lA, hiB, wiB, lB;
    if (br == 0) {
        hiA = rAc / 7;  wiA = rAc - hiA * 7;  lA = hiA * WW + w16 * 7 + wiA;
        hiB = rBc / 7;  wiB = rBc - hiB * 7;  lB = hiB * WW + w16 * 7 + wiB;
    } else {
        hiA = rAc / 112; wiA = rAc - hiA * 112; lA = (w16 * 7 + hiA) * WW + wiA;
        hiB = rBc / 112; wiB = rBc - hiB * 112; lB = (w16 * 7 + hiB) * WW + wiB;
    }
    int rbA = (hiA + Hsp - 1) * W2 + wiA + Wsp - 1;
    int rbB = (hiB + Hsp - 1) * W2 + wiB + Wsp - 1;

    u64 qA[12], qB[12];
    {
        const float* qp = qkv + ((long)(b * LL + lA)) * 576 + cbase;
#pragma unroll
        for (int d = 0; d < 12; d++)
            qA[d] = pack2(qp[2 * d] * scale, qp[2 * d + 1] * scale);
    }
    if (ROWS == 2) {
        const float* qp = qkv + ((long)(b * LL + lB)) * 576 + cbase;
#pragma unroll
        for (int d = 0; d < 12; d++)
            qB[d] = pack2(qp[2 * d] * scale, qp[2 * d + 1] * scale);
    }

    float mA = -1e30f, eA = 0.f, mB = -1e30f, eB = 0.f;
    u64 OA[12], OB[12];
#pragma unroll
    for (int d = 0; d < 12; d++) { OA[d] = 0ull; OB[d] = 0ull; }

    for (int j0 = 0; j0 < NTOK; j0 += 8) {
        float sA[8], sB[8];
#pragma unroll
        for (int jj = 0; jj < 8; jj++) {
            int j = j0 + jj;
            const ulonglong2* kp = (const ulonglong2*)(Ks + j * HD_);
            u64 psA = 0ull, psB = 0ull;
#pragma unroll
            for (int i = 0; i < 6; i++) {
                ulonglong2 kk = kp[i];
                ffma2(psA, kk.x, qA[2 * i]);
                ffma2(psA, kk.y, qA[2 * i + 1]);
                if (ROWS == 2) {
                    ffma2(psB, kk.x, qB[2 * i]);
                    ffma2(psB, kk.y, qB[2 * i + 1]);
                }
            }
            int roff = Rj[j];
            sA[jj] = lo2(psA) + hi2(psA) + Ps[rbA - roff];
            if (ROWS == 2)
                sB[jj] = lo2(psB) + hi2(psB) + Ps[rbB - roff];
        }
        // chunk max + rescale
        float cmA = sA[0], cmB = (ROWS == 2) ? sB[0] : 0.f;
#pragma unroll
        for (int jj = 1; jj < 8; jj++) {
            cmA = fmaxf(cmA, sA[jj]);
            if (ROWS == 2) cmB = fmaxf(cmB, sB[jj]);
        }
        float nmA = fmaxf(mA, cmA);
        float fA = __expf(mA - nmA);
        mA = nmA; eA *= fA;
        u64 fAd = pack2(fA, fA);
#pragma unroll
        for (int d = 0; d < 12; d++) mul2(OA[d], fAd);
        if (ROWS == 2) {
            float nmB = fmaxf(mB, cmB);
            float fB = __expf(mB - nmB);
            mB = nmB; eB *= fB;
            u64 fBd = pack2(fB, fB);
#pragma unroll
            for (int d = 0; d < 12; d++) mul2(OB[d], fBd);
        }
        // AV
#pragma unroll
        for (int jj = 0; jj < 8; jj++) {
            int j = j0 + jj;
            float pA = __expf(sA[jj] - mA); eA += pA;
            u64 pAd = pack2(pA, pA);
            float pB = 0.f; u64 pBd = 0ull;
            if (ROWS == 2) {
                pB = __expf(sB[jj] - mB); eB += pB;
                pBd = pack2(pB, pB);
            }
            const ulonglong2* vp = (const ulonglong2*)(Vs + j * HD_);
#pragma unroll
            for (int i = 0; i < 6; i++) {
                ulonglong2 vv = vp[i];
                ffma2(OA[2 * i],     vv.x, pAd);
                ffma2(OA[2 * i + 1], vv.y, pAd);
                if (ROWS == 2) {
                    ffma2(OB[2 * i],     vv.x, pBd);
                    ffma2(OB[2 * i + 1], vv.y, pBd);
                }
            }
        }
    }
    if (actA) {
        float inv = 1.f / eA;
        float* o = att_out + ((long)(b * LL + lA)) * CC + cbase;
#pragma unroll
        for (int i = 0; i < 6; i++) {
            u64 a = OA[2 * i], c = OA[2 * i + 1];
            *(float4*)(o + i * 4) = make_float4(lo2(a) * inv, hi2(a) * inv,
                                                lo2(c) * inv, hi2(c) * inv);
        }
    }
    if (ROWS == 2 && actB) {
        float inv = 1.f / eB;
        float* o = att_out + ((long)(b * LL + lB)) * CC + cbase;
#pragma unroll
        for (int i = 0; i < 6; i++) {
            u64 a = OB[2 * i], c = OB[2 * i + 1];
            *(float4*)(o + i * 4) = make_float4(lo2(a) * inv, hi2(a) * inv,
                                                lo2(c) * inv, hi2(c) * inv);
        }
    }
}

__global__ __launch_bounds__(256) void attn_kernel(
    const float* __restrict__ qkv, const float* __restrict__ pos,
    float* __restrict__ att_out)
{
    extern __shared__ float sm[];
    float* Ks = sm;                          // 784*24
    float* Vs = Ks + NTOK * HD_;             // 784*24
    float* Ps = Vs + NTOK * HD_;             // 2899
    int*   Rj = (int*)(Ps + NPOS);           // 784

    int bx   = blockIdx.x;
    int br   = bx >> 7;
    int rem  = bx & 127;
    int win  = rem >> 2;
    int head = rem & 3;
    int b    = win >> 4, w16 = win & 15;
    int tid  = threadIdx.x, lane = tid & 31, warp = tid >> 5;
    int cbase = br * CB + head * HD_;

    const int Hsp = br ? 7 : 112;
    const int Wsp = br ? 112 : 7;
    const int W2  = 2 * Wsp - 1;

    for (int idx = tid; idx < NTOK * HD_; idx += 256) {
        int j = idx / HD_, d = idx - j * HD_;
        int h, w;
        if (br == 0) { int hj = j / 7;   h = hj;           w = w16 * 7 + (j - hj * 7); }
        else         { int hj = j / 112; h = w16 * 7 + hj; w = j - hj * 112; }
        long base = ((long)(b * LL + h * WW + w)) * 576 + cbase + d;
        Ks[j * HD_ + d] = qkv[base + 192];
        Vs[j * HD_ + d] = qkv[base + 384];
    }
    for (int rr = tid; rr < NPOS; rr += 256)
        Ps[rr] = pos[(br * NPOS + rr) * 4 + head];
    for (int j = tid; j < NTOK; j += 256) {
        int hj, wj;
        if (br == 0) { hj = j / 7;   wj = j - hj * 7;   }
        else         { hj = j / 112; wj = j - hj * 112; }
        Rj[j] = hj * W2 + wj;
    }
    __syncthreads();

    // 13 passes of 64 rows (last covers rows 768..783).
    // schedule per warp: {w}, {w+8 if w<4}, {12 if w==7}  -> per-SMSP 3/3/3/3.25
    attn_pass<2>(warp * 64, lane, br, b, w16, cbase, qkv, Ks, Vs, Ps, Rj,
                 att_out, Hsp, Wsp, W2);
    if (warp < 4)
        attn_pass<2>((warp + 8) * 64, lane, br, b, w16, cbase, qkv, Ks, Vs, Ps,
                     Rj, att_out, Hsp, Wsp, W2);
    if (warp == 7)
        attn_pass<1>(12 * 64, lane, br, b, w16, cbase, qkv, Ks, Vs, Ps, Rj,
                     att_out, Hsp, Wsp, W2);
}

// -------------------------- SGEMM (NT) with FFMA2 --------------------------
// out[M,N] = A[M,K] @ W[N,K]^T. BM=128, BN=64, BK=16, 256 thr.
// Conflict-free SMEM layout; b duplicated into register pairs (alu-pipe MOVs).
__device__ __forceinline__ float gelu_f(float x)
{
    return 0.5f * x * (1.f + erff(x * 0.7071067811865476f));
}

template <int MODE>
__global__ __launch_bounds__(256) void gemm_kernel(
    const float* __restrict__ A, const float* __restrict__ Wt,
    const float* __restrict__ bias, const float* __restrict__ res,
    float* __restrict__ out, int N, int K)
{
    __shared__ __align__(16) float As[16][128];
    __shared__ __align__(16) float Bs[16][64];
    const int m0 = blockIdx.x * 128;
    const int n0 = blockIdx.y * 64;
    const int tid = threadIdx.x;
    const int tx = tid & 15, ty = tid >> 4;

    u64 c2[4][4];
#pragma unroll
    for (int u = 0; u < 4; u++)
#pragma unroll
        for (int v = 0; v < 4; v++) c2[u][v] = 0ull;

    for (int kt = 0; kt < K; kt += 16) {
#pragma unroll
        for (int i = 0; i < 2; i++) {
            int f = tid + i * 256;
            int m = f >> 2, k4 = (f & 3) * 4;
            float4 a = *(const float4*)&A[(long)(m0 + m) * K + kt + k4];
            As[k4 + 0][m] = a.x; As[k4 + 1][m] = a.y;
            As[k4 + 2][m] = a.z; As[k4 + 3][m] = a.w;
        }
        {
            int n = tid >> 2, k4 = (tid & 3) * 4;
            float4 bv = *(const float4*)&Wt[(long)(n0 + n) * K + kt + k4];
            Bs[k4 + 0][n] = bv.x; Bs[k4 + 1][n] = bv.y;
            Bs[k4 + 2][n] = bv.z; Bs[k4 + 3][n] = bv.w;
        }
        __syncthreads();
#pragma unroll
        for (int kk = 0; kk < 16; kk++) {
            ulonglong2 aA = *(const ulonglong2*)&As[kk][ty * 8];
            ulonglong2 aB = *(const ulonglong2*)&As[kk][ty * 8 + 4];
            float4 bv = *(const float4*)&Bs[kk][tx * 4];
            u64 b0 = pack2(bv.x, bv.x);
            u64 b1 = pack2(bv.y, bv.y);
            u64 b2 = pack2(bv.z, bv.z);
            u64 b3 = pack2(bv.w, bv.w);
            ffma2(c2[0][0], aA.x, b0); ffma2(c2[0][1], aA.x, b1);
            ffma2(c2[0][2], aA.x, b2); ffma2(c2[0][3], aA.x, b3);
            ffma2(c2[1][0], aA.y, b0); ffma2(c2[1][1], aA.y, b1);
            ffma2(c2[1][2], aA.y, b2); ffma2(c2[1][3], aA.y, b3);
            ffma2(c2[2][0], aB.x, b0); ffma2(c2[2][1], aB.x, b1);
            ffma2(c2[2][2], aB.x, b2); ffma2(c2[2][3], aB.x, b3);
            ffma2(c2[3][0], aB.y, b0); ffma2(c2[3][1], aB.y, b1);
            ffma2(c2[3][2], aB.y, b2); ffma2(c2[3][3], aB.y, b3);
        }
        __syncthreads();
    }

    float4 bb = make_float4(0.f, 0.f, 0.f, 0.f);
    if (MODE >= 1) bb = *(const float4*)&bias[n0 + tx * 4];
#pragma unroll
    for (int u = 0; u < 4; u++) {
#pragma unroll
        for (int rsel = 0; rsel < 2; rsel++) {
            int row = m0 + ty * 8 + 2 * u + rsel;
            long rowoff = (long)row * N + n0 + tx * 4;
            float4 o;
            o.x = rsel ? hi2(c2[u][0]) : lo2(c2[u][0]);
            o.y = rsel ? hi2(c2[u][1]) : lo2(c2[u][1]);
            o.z = rsel ? hi2(c2[u][2]) : lo2(c2[u][2]);
            o.w = rsel ? hi2(c2[u][3]) : lo2(c2[u][3]);
            if (MODE >= 1) { o.x += bb.x; o.y += bb.y; o.z += bb.z; o.w += bb.w; }
            if (MODE == 1 || MODE == 3) {
                float4 rr = *(const float4*)&res[rowoff];
                o.x += rr.x; o.y += rr.y; o.z += rr.z; o.w += rr.w;
            }
            if (MODE == 2) {
                o.x = gelu_f(o.x); o.y = gelu_f(o.y);
                o.z = gelu_f(o.z); o.w = gelu_f(o.w);
            }
            *(float4*)&out[rowoff] = o;
        }
    }
}

// -------------------------- launch -----------------------------------------
extern "C" void kernel_launch(void* const* d_in, const int* in_sizes, int n_in,
                              void* d_out, int out_size)
{
    const float* x      = (const float*)d_in[0];
    const float* n1w    = (const float*)d_in[1];
    const float* n1b    = (const float*)d_in[2];
    const float* qkv_w  = (const float*)d_in[3];
    const float* proj_w = (const float*)d_in[4];
    const float* proj_b = (const float*)d_in[5];
    const float* n2w    = (const float*)d_in[6];
    const float* n2b    = (const float*)d_in[7];
    const float* fc1_w  = (const float*)d_in[8];
    const float* fc1_b  = (const float*)d_in[9];
    const float* fc2_w  = (const float*)d_in[10];
    const float* fc2_b  = (const float*)d_in[11];
    const float* pproj_w = (const float*)d_in[12];
    const float* pproj_b = (const float*)d_in[13];
    const float* pln1_w = (const float*)d_in[14];
    const float* pln1_b = (const float*)d_in[15];
    const float* pfc1_w = (const float*)d_in[16];
    const float* pfc1_b = (const float*)d_in[17];
    const float* pln2_w = (const float*)d_in[18];
    const float* pln2_b = (const float*)d_in[19];
    const float* pfc2_w = (const float*)d_in[20];
    const float* pfc2_b = (const float*)d_in[21];
    const float* pln3_w = (const float*)d_in[22];
    const float* pln3_b = (const float*)d_in[23];
    const float* pfc3_w = (const float*)d_in[24];
    const float* pfc3_b = (const float*)d_in[25];
    float* out = (float*)d_out;

    float *img, *qkvb, *att, *xo, *y, *hbuf, *pos;
    cudaGetSymbolAddress((void**)&img,  g_img);
    cudaGetSymbolAddress((void**)&qkvb, g_qkv);
    cudaGetSymbolAddress((void**)&att,  g_att);
    cudaGetSymbolAddress((void**)&xo,   g_xo);
    cudaGetSymbolAddress((void**)&y,    g_y);
    cudaGetSymbolAddress((void**)&hbuf, g_h);
    cudaGetSymbolAddress((void**)&pos,  g_pos);

    cudaFuncSetAttribute(attn_kernel,
                         cudaFuncAttributeMaxDynamicSharedMemorySize, ATTN_SMEM);

    pos_mlp_kernel<<<(2 * NPOS + 127) / 128, 128>>>(
        pproj_w, pproj_b, pln1_w, pln1_b, pfc1_w, pfc1_b,
        pln2_w, pln2_b, pfc2_w, pfc2_b, pln3_w, pln3_b, pfc3_w, pfc3_b, pos);
    ln_kernel<<<MROWS / 8, 256>>>(x, n1w, n1b, img);
    gemm_kernel<0><<<dim3(MROWS / 128, 576 / 64), 256>>>(
        img, qkv_w, nullptr, nullptr, qkvb, 576, 192);
    attn_kernel<<<256, 256, ATTN_SMEM>>>(qkvb, pos, att);
    gemm_kernel<1><<<dim3(MROWS / 128, 192 / 64), 256>>>(
        att, proj_w, proj_b, x, xo, 192, 192);
    ln_kernel<<<MROWS / 8, 256>>>(xo, n2w, n2b, y);
    gemm_kernel<2><<<dim3(MROWS / 128, HIDDEN / 64), 256>>>(
        y, fc1_w, fc1_b, nullptr, hbuf, HIDDEN, 192);
    gemm_kernel<3><<<dim3(MROWS / 128, 192 / 64), 256>>>(
        hbuf, fc2_w, fc2_b, xo, out, 192, HIDDEN);
}